// round 14
// baseline (speedup 1.0000x reference)
#include <cuda_runtime.h>
#include <cuda_fp16.h>
#include <math.h>
#include <stdint.h>

// HardTripletLoss on GB300 (base sm_103 target): HMMA fp16 Gram GEMM + fused
// hardest pos/neg + fused finalize. B=4096, D=512, 64 classes, margin=0.5.
// R14: 512-thread CTAs, 4x4 grid of 32x32 warp tiles -> 32 warps/SM (2 CTAs)
// to fix the latency-bound 33% issue rate. 2 launches total.

#define B_SZ 4096
#define D_SZ 512
#define BM 128
#define BN 128
#define NB (B_SZ / BM)              /* 32 block-rows */
#define NTILES (NB * (NB + 1) / 2)  /* 528 upper-triangular tiles */
#define MARGIN_F 0.5f
#define NTHREADS 512

#define KCHUNK 64                        /* fp16 per K chunk (128B rows, SW128) */
#define NCHUNK (D_SZ / KCHUNK)           /* 8 */
#define TILE_BYTES (128 * KCHUNK * 2)    /* 16384 */
#define BUF_BYTES  (2 * TILE_BYTES)      /* A, B tiles = 32768 */
#define SMEM_DYN   (2 * BUF_BYTES + 1024)

// ------------------------- device scratch -------------------------
__device__ float        g_norms[B_SZ];
__device__ int          g_hp_bits[B_SZ];
__device__ int          g_hn_bits[B_SZ];
__device__ int          g_labels[B_SZ];
__device__ unsigned int g_tiles_done;

__device__ __half  g_xh[B_SZ * D_SZ];

// ------------------------- PTX helpers -------------------------
__device__ __forceinline__ uint32_t smem_u32(const void* p) {
    uint32_t a;
    asm("{ .reg .u64 t; cvta.to.shared.u64 t, %1; cvt.u32.u64 %0, t; }" : "=r"(a) : "l"(p));
    return a;
}
#define CP_ASYNC16(dst, src) \
    asm volatile("cp.async.cg.shared.global [%0], [%1], 16;" :: "r"(dst), "l"(src) : "memory")
#define CP_ASYNC_COMMIT() asm volatile("cp.async.commit_group;" ::: "memory")
#define CP_ASYNC_WAIT(n)  asm volatile("cp.async.wait_group %0;" :: "n"(n) : "memory")

__device__ __forceinline__ void ldsm_x4(uint32_t* r, uint32_t addr) {
    asm volatile("ldmatrix.sync.aligned.m8n8.x4.shared.b16 {%0,%1,%2,%3}, [%4];"
        : "=r"(r[0]), "=r"(r[1]), "=r"(r[2]), "=r"(r[3]) : "r"(addr));
}
__device__ __forceinline__ void mma16816(float* c, const uint32_t* a, const uint32_t* b) {
    asm volatile("mma.sync.aligned.m16n8k16.row.col.f32.f16.f16.f32 "
        "{%0,%1,%2,%3}, {%4,%5,%6,%7}, {%8,%9}, {%0,%1,%2,%3};"
        : "+f"(c[0]), "+f"(c[1]), "+f"(c[2]), "+f"(c[3])
        : "r"(a[0]), "r"(a[1]), "r"(a[2]), "r"(a[3]), "r"(b[0]), "r"(b[1]));
}

// ------------------------- fused prep -------------------------
// All blocks: row norms + fp16 convert + hp/hn init (one warp per row).
// Block 0 additionally: label dtype detect + normalize, reset done-counter.
__global__ void prep_kernel(const float* __restrict__ X, const void* __restrict__ labp) {
    if (blockIdx.x == 0) {
        __shared__ int is64;
        if (threadIdx.x == 0) {
            const long long* lab64 = (const long long*)labp;
            int ok = 1;
            #pragma unroll
            for (int k = 0; k < 16; k++) {
                long long v = lab64[k];
                if (v < 0 || v >= (1LL << 31)) ok = 0;
            }
            is64 = ok;
            g_tiles_done = 0u;
        }
        __syncthreads();
        const int use64 = is64;
        #pragma unroll
        for (int i = 0; i < B_SZ / 256; i++) {
            int idx = threadIdx.x + i * 256;
            g_labels[idx] = use64 ? (int)((const long long*)labp)[idx]
                                  : ((const int*)labp)[idx];
        }
    }

    const int w    = blockIdx.x * 8 + (threadIdx.x >> 5);
    const int lane = threadIdx.x & 31;
    const float4* row = (const float4*)(X + (size_t)w * D_SZ);
    uint2*        dst = (uint2*)(g_xh + (size_t)w * D_SZ);
    float s = 0.f;
    #pragma unroll
    for (int i = 0; i < 4; i++) {
        float4 v = row[lane + 32 * i];
        s = fmaf(v.x, v.x, s);
        s = fmaf(v.y, v.y, s);
        s = fmaf(v.z, v.z, s);
        s = fmaf(v.w, v.w, s);
        __half h[4];
        h[0] = __float2half_rn(v.x);
        h[1] = __float2half_rn(v.y);
        h[2] = __float2half_rn(v.z);
        h[3] = __float2half_rn(v.w);
        dst[lane + 32 * i] = *(uint2*)h;
    }
    #pragma unroll
    for (int m = 16; m >= 1; m >>= 1)
        s += __shfl_down_sync(0xffffffffu, s, m);
    if (lane == 0) {
        g_norms[w]   = s;
        g_hp_bits[w] = (int)0xFF800000;  // -inf
        g_hn_bits[w] = 0x7F800000;       // +inf
    }
}

// ------------------------- chunk loader -------------------------
// 2 tiles (A, B), 128 rows x 64 fp16 each (128B rows), SW128 swizzled.
__device__ __forceinline__ void load_chunk(int chunk, uint32_t bufBase,
                                           int rowBase, int colBase, int tid) {
    const int k0 = chunk * KCHUNK;
    const __half* srcA = g_xh + (size_t)rowBase * D_SZ;
    const __half* srcB = g_xh + (size_t)colBase * D_SZ;
    #pragma unroll
    for (int i = 0; i < 4; i++) {
        int seg  = tid + i * NTHREADS;     // 0..2047
        int c16  = seg & 7;                // 16B segment within row
        int row  = (seg >> 3) & 127;
        int tile = seg >> 10;              // 0 = A, 1 = B
        uint32_t off = (uint32_t)(row * 128 + c16 * 16);
        uint32_t sw  = off ^ ((off >> 3) & 0x70);
        uint32_t dst = bufBase + (uint32_t)tile * TILE_BYTES + sw;
        const __half* base = tile ? srcB : srcA;
        const char* src = (const char*)base + ((size_t)row * D_SZ + k0 + c16 * 8) * 2;
        CP_ASYNC16(dst, src);
    }
    CP_ASYNC_COMMIT();
}

// ------------------------- main tensor-core tile kernel -------------------------
__global__ __launch_bounds__(NTHREADS, 2) void tile_kernel(float* __restrict__ out) {
    extern __shared__ char dsmem[];
    __shared__ int   labB[BN];
    __shared__ float nrmB[BN];
    __shared__ int   lastFlag;
    __shared__ float redS[16];
    __shared__ int   redC[16];

    // ---- triangular tile decode: blockIdx.x -> (by, bx), bx >= by ----
    const int t = blockIdx.x;
    float ff = (float)(2 * NB + 1);
    int by = (int)((ff - sqrtf(ff * ff - 8.0f * (float)t)) * 0.5f);
    if (by < 0) by = 0;
    if (by > NB - 1) by = NB - 1;
    while (by > 0 && (by * NB - by * (by - 1) / 2) > t) by--;
    while (((by + 1) * NB - (by + 1) * by / 2) <= t) by++;
    const int bx   = by + (t - (by * NB - by * (by - 1) / 2));
    const bool diag = (bx == by);

    const int rowBase = by * BM;
    const int colBase = bx * BN;
    const int tid  = threadIdx.x;
    const int wid  = tid >> 5;
    const int lane = tid & 31;

    uint32_t dynBase = (smem_u32(dsmem) + 1023u) & ~1023u;

    if (tid < BN) {
        labB[tid] = g_labels[colBase + tid];
        nrmB[tid] = g_norms[colBase + tid];
    }

    // ---- prologue loads ----
    load_chunk(0, dynBase, rowBase, colBase, tid);
    load_chunk(1, dynBase + BUF_BYTES, rowBase, colBase, tid);

    // ---- per-thread ldmatrix address parts ----
    const int aRowIn = (lane & 7) + ((lane >> 3) & 1) * 8;
    const int aKH    = ((lane >> 4) & 1) * 16;            // bytes
    const int bNIn = (lane & 7) + ((lane >> 4) & 1) * 8;
    const int bKH  = ((lane >> 3) & 1) * 16;              // bytes

    // 4x4 warp grid of 32x32 warp tiles
    const int warpRow0 = (wid & 3) * 32;                  // rows within tile
    const int warpCol0 = (wid >> 2) * 32;                 // cols within tile

    uint32_t aOff[2];
    #pragma unroll
    for (int fm = 0; fm < 2; fm++)
        aOff[fm] = (uint32_t)(warpRow0 + fm * 16 + aRowIn) * 128u;
    const uint32_t aMsk = (uint32_t)(aRowIn & 7) << 4;
    uint32_t bOff[2];
    bOff[0] = (uint32_t)(warpCol0 + bNIn) * 128u;
    bOff[1] = (uint32_t)(warpCol0 + 16 + bNIn) * 128u;
    const uint32_t bMsk = (uint32_t)(bNIn & 7) << 4;

    float Cacc[2][4][4];
    #pragma unroll
    for (int i = 0; i < 2; i++)
        #pragma unroll
        for (int j = 0; j < 4; j++)
            #pragma unroll
            for (int k = 0; k < 4; k++) Cacc[i][j][k] = 0.f;

    // ---- pipelined main loop over 8 K-chunks ----
    for (int c = 0; c < NCHUNK; c++) {
        if (c < NCHUNK - 1) { CP_ASYNC_WAIT(1); } else { CP_ASYNC_WAIT(0); }
        __syncthreads();                       // chunk c resident (and labB on c==0)

        const uint32_t bb = dynBase + (uint32_t)(c & 1) * BUF_BYTES;
        const uint32_t sA = bb;
        const uint32_t sB = bb + TILE_BYTES;

        #pragma unroll
        for (int ks = 0; ks < 4; ks++) {
            const uint32_t akb = ((uint32_t)(ks * 32 + aKH)) ^ aMsk;
            const uint32_t bkb = ((uint32_t)(ks * 32 + bKH)) ^ bMsk;
            uint32_t bh[8];
            ldsm_x4(bh,     sB + bOff[0] + bkb);
            ldsm_x4(bh + 4, sB + bOff[1] + bkb);
            #pragma unroll
            for (int fm = 0; fm < 2; fm++) {
                uint32_t a[4];
                ldsm_x4(a, sA + aOff[fm] + akb);
                #pragma unroll
                for (int fn = 0; fn < 4; fn++) mma16816(Cacc[fm][fn], a, bh + fn * 2);
            }
        }

        if (c + 2 < NCHUNK) {
            __syncthreads();                   // all warps done reading this buffer
            load_chunk(c + 2, dynBase + (uint32_t)(c & 1) * BUF_BYTES,
                       rowBase, colBase, tid);
        }
    }

    // ---- epilogue: distances + hardest pos/neg from register fragments ----
    const float NEG_INF = __int_as_float(0xFF800000);
    const float POS_INF = __int_as_float(0x7F800000);
    const int quad = lane >> 2;      // 0..7  (row within 8-row group)
    const int pos  = lane & 3;       // 0..3  (col pair)

    int   laR[4], giR[4];
    float naR[4];
    #pragma unroll
    for (int fm = 0; fm < 2; fm++)
        #pragma unroll
        for (int ar = 0; ar < 2; ar++) {
            int gi = rowBase + warpRow0 + fm * 16 + ar * 8 + quad;
            giR[fm * 2 + ar] = gi;
            laR[fm * 2 + ar] = g_labels[gi];
            naR[fm * 2 + ar] = g_norms[gi];
        }
    int   lbC[8], gjC[8];
    float nbC[8];
    #pragma unroll
    for (int fn = 0; fn < 4; fn++)
        #pragma unroll
        for (int cb = 0; cb < 2; cb++) {
            int cl = warpCol0 + fn * 8 + pos * 2 + cb;
            gjC[fn * 2 + cb] = colBase + cl;
            lbC[fn * 2 + cb] = labB[cl];
            nbC[fn * 2 + cb] = nrmB[cl];
        }

    float hpR[4], hnR[4], hpc[8], hnc[8];
    #pragma unroll
    for (int i = 0; i < 4; i++) { hpR[i] = NEG_INF; hnR[i] = POS_INF; }
    #pragma unroll
    for (int i = 0; i < 8; i++) { hpc[i] = NEG_INF; hnc[i] = POS_INF; }

    #pragma unroll
    for (int fm = 0; fm < 2; fm++)
        #pragma unroll
        for (int fn = 0; fn < 4; fn++)
            #pragma unroll
            for (int ar = 0; ar < 2; ar++)
                #pragma unroll
                for (int cb = 0; cb < 2; cb++) {
                    int ri = fm * 2 + ar, ci = fn * 2 + cb;
                    float dot = Cacc[fm][fn][ar * 2 + cb];
                    float sq  = fmaxf(fmaf(-2.f, dot, naR[ri] + nbC[ci]), 0.f);
                    float d   = sqrtf(sq);
                    if (laR[ri] == lbC[ci]) {
                        if (giR[ri] != gjC[ci]) {
                            hpR[ri] = fmaxf(hpR[ri], d);
                            hpc[ci] = fmaxf(hpc[ci], d);
                        }
                    } else {
                        hnR[ri] = fminf(hnR[ri], d);
                        hnc[ci] = fminf(hnc[ci], d);
                    }
                }

    // row stats: reduce over the 4 'pos' lanes sharing a row
    #pragma unroll
    for (int i = 0; i < 4; i++) {
        float a = hpR[i], b = hnR[i];
        a = fmaxf(a, __shfl_xor_sync(0xffffffffu, a, 1));
        a = fmaxf(a, __shfl_xor_sync(0xffffffffu, a, 2));
        b = fminf(b, __shfl_xor_sync(0xffffffffu, b, 1));
        b = fminf(b, __shfl_xor_sync(0xffffffffu, b, 2));
        if (pos == 0) {
            atomicMax(&g_hp_bits[giR[i]], __float_as_int(a));
            atomicMin(&g_hn_bits[giR[i]], __float_as_int(b));
        }
    }
    // column stats (symmetry): reduce over the 8 'quad' lanes sharing a column
    if (!diag) {
        #pragma unroll
        for (int i = 0; i < 8; i++) {
            float a = hpc[i], b = hnc[i];
            a = fmaxf(a, __shfl_xor_sync(0xffffffffu, a, 4));
            a = fmaxf(a, __shfl_xor_sync(0xffffffffu, a, 8));
            a = fmaxf(a, __shfl_xor_sync(0xffffffffu, a, 16));
            b = fminf(b, __shfl_xor_sync(0xffffffffu, b, 4));
            b = fminf(b, __shfl_xor_sync(0xffffffffu, b, 8));
            b = fminf(b, __shfl_xor_sync(0xffffffffu, b, 16));
            if (quad == 0) {
                atomicMax(&g_hp_bits[gjC[i]], __float_as_int(a));
                atomicMin(&g_hn_bits[gjC[i]], __float_as_int(b));
            }
        }
    }

    // ---- fused finalize: last CTA reduces hp/hn into the scalar loss ----
    __threadfence();                       // make this CTA's atomics visible
    __syncthreads();                       // all threads' atomics issued
    if (tid == 0) {
        unsigned int prev = atomicAdd(&g_tiles_done, 1u);
        lastFlag = (prev == NTILES - 1u);
    }
    __syncthreads();
    if (!lastFlag) return;

    // this CTA observes all other CTAs' atomics (counter was written after
    // their threadfence; atomicAdd ordering gives acquire semantics here)
    float sum = 0.f;
    int   cnt = 0;
    #pragma unroll
    for (int i = 0; i < B_SZ / NTHREADS; i++) {
        int idx = tid + i * NTHREADS;
        int hpb = g_hp_bits[idx];
        int hnb = g_hn_bits[idx];
        if (hpb != (int)0xFF800000 && hnb != 0x7F800000) {
            sum += fmaxf(__int_as_float(hpb) - __int_as_float(hnb) + MARGIN_F, 0.f);
            cnt += 1;
        }
    }
    #pragma unroll
    for (int m = 16; m >= 1; m >>= 1) {
        sum += __shfl_xor_sync(0xffffffffu, sum, m);
        cnt += __shfl_xor_sync(0xffffffffu, cnt, m);
    }
    if (lane == 0) { redS[wid] = sum; redC[wid] = cnt; }
    __syncthreads();
    if (wid == 0) {
        float s2 = (lane < 16) ? redS[lane] : 0.f;
        int   c2 = (lane < 16) ? redC[lane] : 0;
        #pragma unroll
        for (int m = 8; m >= 1; m >>= 1) {
            s2 += __shfl_xor_sync(0xffffffffu, s2, m);
            c2 += __shfl_xor_sync(0xffffffffu, c2, m);
        }
        if (lane == 0) out[0] = (c2 > 0) ? (s2 / (float)c2) : 0.f;
    }
}

// ------------------------- launch -------------------------
extern "C" void kernel_launch(void* const* d_in, const int* in_sizes, int n_in,
                              void* d_out, int out_size) {
    const float* X    = (const float*)d_in[0];
    const void*  labp = d_in[1];
    float*       out  = (float*)d_out;

    // idempotent, host-side, not a stream op: safe under graph capture
    cudaFuncSetAttribute(tile_kernel, cudaFuncAttributeMaxDynamicSharedMemorySize, SMEM_DYN);

    prep_kernel<<<B_SZ / 8, 256>>>(X, labp);
    tile_kernel<<<NTILES, NTHREADS, SMEM_DYN>>>(out);
}

// round 15
// speedup vs baseline: 1.0603x; 1.0603x over previous
#include <cuda_runtime.h>
#include <cuda_fp16.h>
#include <math.h>
#include <stdint.h>

// HardTripletLoss on GB300 (base sm_103 target): HMMA fp16 Gram GEMM + fused
// hardest pos/neg + fused finalize. B=4096, D=512, 64 classes, margin=0.5.
// R15: revert to R13 shape (256 thr, 64x32 warp tiles — measured best), add
// 3-stage cp.async pipeline with ONE __syncthreads per chunk, prep MLP fix.

#define B_SZ 4096
#define D_SZ 512
#define BM 128
#define BN 128
#define NB (B_SZ / BM)              /* 32 block-rows */
#define NTILES (NB * (NB + 1) / 2)  /* 528 upper-triangular tiles */
#define MARGIN_F 0.5f

#define KCHUNK 64                        /* fp16 per K chunk (128B rows, SW128) */
#define NCHUNK (D_SZ / KCHUNK)           /* 8 */
#define TILE_BYTES (128 * KCHUNK * 2)    /* 16384 */
#define BUF_BYTES  (2 * TILE_BYTES)      /* A, B tiles = 32768 */
#define NSTAGE 3
#define SMEM_DYN   (NSTAGE * BUF_BYTES + 1024)

// ------------------------- device scratch -------------------------
__device__ float        g_norms[B_SZ];
__device__ int          g_hp_bits[B_SZ];
__device__ int          g_hn_bits[B_SZ];
__device__ int          g_labels[B_SZ];
__device__ unsigned int g_tiles_done;

__device__ __half  g_xh[B_SZ * D_SZ];

// ------------------------- PTX helpers -------------------------
__device__ __forceinline__ uint32_t smem_u32(const void* p) {
    uint32_t a;
    asm("{ .reg .u64 t; cvta.to.shared.u64 t, %1; cvt.u32.u64 %0, t; }" : "=r"(a) : "l"(p));
    return a;
}
#define CP_ASYNC16(dst, src) \
    asm volatile("cp.async.cg.shared.global [%0], [%1], 16;" :: "r"(dst), "l"(src) : "memory")
#define CP_ASYNC_COMMIT() asm volatile("cp.async.commit_group;" ::: "memory")
#define CP_ASYNC_WAIT(n)  asm volatile("cp.async.wait_group %0;" :: "n"(n) : "memory")

__device__ __forceinline__ void ldsm_x4(uint32_t* r, uint32_t addr) {
    asm volatile("ldmatrix.sync.aligned.m8n8.x4.shared.b16 {%0,%1,%2,%3}, [%4];"
        : "=r"(r[0]), "=r"(r[1]), "=r"(r[2]), "=r"(r[3]) : "r"(addr));
}
__device__ __forceinline__ void mma16816(float* c, const uint32_t* a, const uint32_t* b) {
    asm volatile("mma.sync.aligned.m16n8k16.row.col.f32.f16.f16.f32 "
        "{%0,%1,%2,%3}, {%4,%5,%6,%7}, {%8,%9}, {%0,%1,%2,%3};"
        : "+f"(c[0]), "+f"(c[1]), "+f"(c[2]), "+f"(c[3])
        : "r"(a[0]), "r"(a[1]), "r"(a[2]), "r"(a[3]), "r"(b[0]), "r"(b[1]));
}

// ------------------------- fused prep -------------------------
// All blocks: row norms + fp16 convert + hp/hn init (one warp per row).
// Block 0 additionally: label dtype detect + normalize, reset done-counter.
__global__ void prep_kernel(const float* __restrict__ X, const void* __restrict__ labp) {
    if (blockIdx.x == 0) {
        __shared__ int is64;
        if (threadIdx.x == 0) {
            const long long* lab64 = (const long long*)labp;
            int ok = 1;
            #pragma unroll
            for (int k = 0; k < 16; k++) {
                long long v = lab64[k];
                if (v < 0 || v >= (1LL << 31)) ok = 0;
            }
            is64 = ok;
            g_tiles_done = 0u;
        }
        __syncthreads();
        const int use64 = is64;
        #pragma unroll
        for (int i = 0; i < B_SZ / 256; i++) {
            int idx = threadIdx.x + i * 256;
            g_labels[idx] = use64 ? (int)((const long long*)labp)[idx]
                                  : ((const int*)labp)[idx];
        }
    }

    const int w    = blockIdx.x * 8 + (threadIdx.x >> 5);
    const int lane = threadIdx.x & 31;
    const float4* row = (const float4*)(X + (size_t)w * D_SZ);
    uint2*        dst = (uint2*)(g_xh + (size_t)w * D_SZ);

    // issue all loads first (MLP=4), then compute
    float4 v[4];
    #pragma unroll
    for (int i = 0; i < 4; i++) v[i] = row[lane + 32 * i];

    float s = 0.f;
    #pragma unroll
    for (int i = 0; i < 4; i++) {
        s = fmaf(v[i].x, v[i].x, s);
        s = fmaf(v[i].y, v[i].y, s);
        s = fmaf(v[i].z, v[i].z, s);
        s = fmaf(v[i].w, v[i].w, s);
        __half h[4];
        h[0] = __float2half_rn(v[i].x);
        h[1] = __float2half_rn(v[i].y);
        h[2] = __float2half_rn(v[i].z);
        h[3] = __float2half_rn(v[i].w);
        dst[lane + 32 * i] = *(uint2*)h;
    }
    #pragma unroll
    for (int m = 16; m >= 1; m >>= 1)
        s += __shfl_down_sync(0xffffffffu, s, m);
    if (lane == 0) {
        g_norms[w]   = s;
        g_hp_bits[w] = (int)0xFF800000;  // -inf
        g_hn_bits[w] = 0x7F800000;       // +inf
    }
}

// ------------------------- chunk loader -------------------------
// 2 tiles (A, B), 128 rows x 64 fp16 each (128B rows), SW128 swizzled.
__device__ __forceinline__ void load_chunk(int chunk, uint32_t bufBase,
                                           int rowBase, int colBase, int tid) {
    const int k0 = chunk * KCHUNK;
    const __half* srcA = g_xh + (size_t)rowBase * D_SZ;
    const __half* srcB = g_xh + (size_t)colBase * D_SZ;
    #pragma unroll
    for (int i = 0; i < 8; i++) {
        int seg  = tid + i * 256;          // 0..2047
        int c16  = seg & 7;                // 16B segment within row
        int row  = (seg >> 3) & 127;
        int tile = seg >> 10;              // 0 = A, 1 = B
        uint32_t off = (uint32_t)(row * 128 + c16 * 16);
        uint32_t sw  = off ^ ((off >> 3) & 0x70);
        uint32_t dst = bufBase + (uint32_t)tile * TILE_BYTES + sw;
        const __half* base = tile ? srcB : srcA;
        const char* src = (const char*)base + ((size_t)row * D_SZ + k0 + c16 * 8) * 2;
        CP_ASYNC16(dst, src);
    }
    CP_ASYNC_COMMIT();
}

// ------------------------- main tensor-core tile kernel -------------------------
__global__ __launch_bounds__(256, 2) void tile_kernel(float* __restrict__ out) {
    extern __shared__ char dsmem[];
    __shared__ int   labB[BN];
    __shared__ float nrmB[BN];
    __shared__ int   lastFlag;
    __shared__ float redS[8];
    __shared__ int   redC[8];

    // ---- triangular tile decode: blockIdx.x -> (by, bx), bx >= by ----
    const int t = blockIdx.x;
    float ff = (float)(2 * NB + 1);
    int by = (int)((ff - sqrtf(ff * ff - 8.0f * (float)t)) * 0.5f);
    if (by < 0) by = 0;
    if (by > NB - 1) by = NB - 1;
    while (by > 0 && (by * NB - by * (by - 1) / 2) > t) by--;
    while (((by + 1) * NB - (by + 1) * by / 2) <= t) by++;
    const int bx   = by + (t - (by * NB - by * (by - 1) / 2));
    const bool diag = (bx == by);

    const int rowBase = by * BM;
    const int colBase = bx * BN;
    const int tid  = threadIdx.x;
    const int wid  = tid >> 5;
    const int lane = tid & 31;

    uint32_t dynBase = (smem_u32(dsmem) + 1023u) & ~1023u;

    if (tid < BN) {
        labB[tid] = g_labels[colBase + tid];
        nrmB[tid] = g_norms[colBase + tid];
    }

    // ---- prologue: fill stages 0 and 1 ----
    load_chunk(0, dynBase, rowBase, colBase, tid);
    load_chunk(1, dynBase + BUF_BYTES, rowBase, colBase, tid);

    // ---- per-thread ldmatrix address parts ----
    const int aRowIn = (lane & 7) + ((lane >> 3) & 1) * 8;
    const int aKH    = ((lane >> 4) & 1) * 16;            // bytes
    const int bNIn = (lane & 7) + ((lane >> 4) & 1) * 8;
    const int bKH  = ((lane >> 3) & 1) * 16;              // bytes

    const int warpRow0 = (wid & 1) * 64;                  // rows within tile
    const int warpCol0 = (wid >> 1) * 32;                 // cols within tile

    uint32_t aOff[4];
    #pragma unroll
    for (int fm = 0; fm < 4; fm++)
        aOff[fm] = (uint32_t)(warpRow0 + fm * 16 + aRowIn) * 128u;
    const uint32_t aMsk = (uint32_t)(aRowIn & 7) << 4;
    uint32_t bOff[2];
    bOff[0] = (uint32_t)(warpCol0 + bNIn) * 128u;
    bOff[1] = (uint32_t)(warpCol0 + 16 + bNIn) * 128u;
    const uint32_t bMsk = (uint32_t)(bNIn & 7) << 4;

    float Cacc[4][4][4];
    #pragma unroll
    for (int i = 0; i < 4; i++)
        #pragma unroll
        for (int j = 0; j < 4; j++)
            #pragma unroll
            for (int k = 0; k < 4; k++) Cacc[i][j][k] = 0.f;

    // ---- 3-stage pipelined main loop: ONE barrier per chunk ----
    // Invariant at iter c: loads issued for chunks <= c+1; stage (c+2)%3
    // holds chunk c-1, whose readers all passed this iteration's barrier.
    #pragma unroll 1
    for (int c = 0; c < NCHUNK; c++) {
        if (c < NCHUNK - 1) { CP_ASYNC_WAIT(1); } else { CP_ASYNC_WAIT(0); }
        __syncthreads();                   // chunk c visible to all warps;
                                           // stage (c+2)%3 free for reuse
        if (c + 2 < NCHUNK)
            load_chunk(c + 2, dynBase + (uint32_t)((c + 2) % NSTAGE) * BUF_BYTES,
                       rowBase, colBase, tid);

        const uint32_t bb = dynBase + (uint32_t)(c % NSTAGE) * BUF_BYTES;
        const uint32_t sA = bb;
        const uint32_t sB = bb + TILE_BYTES;

        #pragma unroll
        for (int ks = 0; ks < 4; ks++) {
            const uint32_t akb = ((uint32_t)(ks * 32 + aKH)) ^ aMsk;
            const uint32_t bkb = ((uint32_t)(ks * 32 + bKH)) ^ bMsk;
            uint32_t bh[8];
            ldsm_x4(bh,     sB + bOff[0] + bkb);
            ldsm_x4(bh + 4, sB + bOff[1] + bkb);
            #pragma unroll
            for (int fm = 0; fm < 4; fm++) {
                uint32_t a[4];
                ldsm_x4(a, sA + aOff[fm] + akb);
                #pragma unroll
                for (int fn = 0; fn < 4; fn++) mma16816(Cacc[fm][fn], a, bh + fn * 2);
            }
        }
    }

    // ---- epilogue: distances + hardest pos/neg from register fragments ----
    const float NEG_INF = __int_as_float(0xFF800000);
    const float POS_INF = __int_as_float(0x7F800000);
    const int quad = lane >> 2;      // 0..7  (row within 8-row group)
    const int pos  = lane & 3;       // 0..3  (col pair)

    int   laR[8], giR[8];
    float naR[8];
    #pragma unroll
    for (int fm = 0; fm < 4; fm++)
        #pragma unroll
        for (int ar = 0; ar < 2; ar++) {
            int gi = rowBase + warpRow0 + fm * 16 + ar * 8 + quad;
            giR[fm * 2 + ar] = gi;
            laR[fm * 2 + ar] = g_labels[gi];
            naR[fm * 2 + ar] = g_norms[gi];
        }
    int   lbC[8], gjC[8];
    float nbC[8];
    #pragma unroll
    for (int fn = 0; fn < 4; fn++)
        #pragma unroll
        for (int cb = 0; cb < 2; cb++) {
            int cl = warpCol0 + fn * 8 + pos * 2 + cb;
            gjC[fn * 2 + cb] = colBase + cl;
            lbC[fn * 2 + cb] = labB[cl];
            nbC[fn * 2 + cb] = nrmB[cl];
        }

    float hpR[8], hnR[8], hpc[8], hnc[8];
    #pragma unroll
    for (int i = 0; i < 8; i++) { hpR[i] = NEG_INF; hnR[i] = POS_INF; hpc[i] = NEG_INF; hnc[i] = POS_INF; }

    #pragma unroll
    for (int fm = 0; fm < 4; fm++)
        #pragma unroll
        for (int fn = 0; fn < 4; fn++)
            #pragma unroll
            for (int ar = 0; ar < 2; ar++)
                #pragma unroll
                for (int cb = 0; cb < 2; cb++) {
                    int ri = fm * 2 + ar, ci = fn * 2 + cb;
                    float dot = Cacc[fm][fn][ar * 2 + cb];
                    float sq  = fmaxf(fmaf(-2.f, dot, naR[ri] + nbC[ci]), 0.f);
                    float d   = sqrtf(sq);
                    if (laR[ri] == lbC[ci]) {
                        if (giR[ri] != gjC[ci]) {
                            hpR[ri] = fmaxf(hpR[ri], d);
                            hpc[ci] = fmaxf(hpc[ci], d);
                        }
                    } else {
                        hnR[ri] = fminf(hnR[ri], d);
                        hnc[ci] = fminf(hnc[ci], d);
                    }
                }

    // row stats: reduce over the 4 'pos' lanes sharing a row
    #pragma unroll
    for (int i = 0; i < 8; i++) {
        float a = hpR[i], b = hnR[i];
        a = fmaxf(a, __shfl_xor_sync(0xffffffffu, a, 1));
        a = fmaxf(a, __shfl_xor_sync(0xffffffffu, a, 2));
        b = fminf(b, __shfl_xor_sync(0xffffffffu, b, 1));
        b = fminf(b, __shfl_xor_sync(0xffffffffu, b, 2));
        if (pos == 0) {
            atomicMax(&g_hp_bits[giR[i]], __float_as_int(a));
            atomicMin(&g_hn_bits[giR[i]], __float_as_int(b));
        }
    }
    // column stats (symmetry): reduce over the 8 'quad' lanes sharing a column
    if (!diag) {
        #pragma unroll
        for (int i = 0; i < 8; i++) {
            float a = hpc[i], b = hnc[i];
            a = fmaxf(a, __shfl_xor_sync(0xffffffffu, a, 4));
            a = fmaxf(a, __shfl_xor_sync(0xffffffffu, a, 8));
            a = fmaxf(a, __shfl_xor_sync(0xffffffffu, a, 16));
            b = fminf(b, __shfl_xor_sync(0xffffffffu, b, 4));
            b = fminf(b, __shfl_xor_sync(0xffffffffu, b, 8));
            b = fminf(b, __shfl_xor_sync(0xffffffffu, b, 16));
            if (quad == 0) {
                atomicMax(&g_hp_bits[gjC[i]], __float_as_int(a));
                atomicMin(&g_hn_bits[gjC[i]], __float_as_int(b));
            }
        }
    }

    // ---- fused finalize: last CTA reduces hp/hn into the scalar loss ----
    __threadfence();                       // make this CTA's atomics visible
    __syncthreads();                       // all threads' atomics issued
    if (tid == 0) {
        unsigned int prev = atomicAdd(&g_tiles_done, 1u);
        lastFlag = (prev == NTILES - 1u);
    }
    __syncthreads();
    if (!lastFlag) return;

    // this CTA observes all other CTAs' atomics (counter was written after
    // their threadfence; atomicAdd ordering gives acquire semantics here)
    float sum = 0.f;
    int   cnt = 0;
    #pragma unroll
    for (int i = 0; i < B_SZ / 256; i++) {
        int idx = tid + i * 256;
        int hpb = g_hp_bits[idx];
        int hnb = g_hn_bits[idx];
        if (hpb != (int)0xFF800000 && hnb != 0x7F800000) {
            sum += fmaxf(__int_as_float(hpb) - __int_as_float(hnb) + MARGIN_F, 0.f);
            cnt += 1;
        }
    }
    #pragma unroll
    for (int m = 16; m >= 1; m >>= 1) {
        sum += __shfl_xor_sync(0xffffffffu, sum, m);
        cnt += __shfl_xor_sync(0xffffffffu, cnt, m);
    }
    if (lane == 0) { redS[wid] = sum; redC[wid] = cnt; }
    __syncthreads();
    if (wid == 0) {
        float s2 = (lane < 8) ? redS[lane] : 0.f;
        int   c2 = (lane < 8) ? redC[lane] : 0;
        #pragma unroll
        for (int m = 4; m >= 1; m >>= 1) {
            s2 += __shfl_xor_sync(0xffffffffu, s2, m);
            c2 += __shfl_xor_sync(0xffffffffu, c2, m);
        }
        if (lane == 0) out[0] = (c2 > 0) ? (s2 / (float)c2) : 0.f;
    }
}

// ------------------------- launch -------------------------
extern "C" void kernel_launch(void* const* d_in, const int* in_sizes, int n_in,
                              void* d_out, int out_size) {
    const float* X    = (const float*)d_in[0];
    const void*  labp = d_in[1];
    float*       out  = (float*)d_out;

    // idempotent, host-side, not a stream op: safe under graph capture
    cudaFuncSetAttribute(tile_kernel, cudaFuncAttributeMaxDynamicSharedMemorySize, SMEM_DYN);

    prep_kernel<<<B_SZ / 8, 256>>>(X, labp);
    tile_kernel<<<NTILES, 256, SMEM_DYN>>>(out);
}

// round 17
// speedup vs baseline: 1.0936x; 1.0315x over previous
#include <cuda_runtime.h>
#include <cuda_fp16.h>
#include <math.h>
#include <stdint.h>

// HardTripletLoss on GB300 (base sm_103 target): HMMA fp16 Gram GEMM + fused
// hardest pos/neg + fused finalize. B=4096, D=512, 64 classes, margin=0.5.
// R16 (resubmit after infra "device busy"): R13 2-stage mainloop (measured
// best); batch all 6 LDSM per ks-step (MLP=6); select in d^2 space, defer
// sqrt to finalize.

#define B_SZ 4096
#define D_SZ 512
#define BM 128
#define BN 128
#define NB (B_SZ / BM)              /* 32 block-rows */
#define NTILES (NB * (NB + 1) / 2)  /* 528 upper-triangular tiles */
#define MARGIN_F 0.5f

#define KCHUNK 64                        /* fp16 per K chunk (128B rows, SW128) */
#define NCHUNK (D_SZ / KCHUNK)           /* 8 */
#define TILE_BYTES (128 * KCHUNK * 2)    /* 16384 */
#define BUF_BYTES  (2 * TILE_BYTES)      /* A, B tiles = 32768 */
#define SMEM_DYN   (2 * BUF_BYTES + 1024)

// ------------------------- device scratch -------------------------
__device__ float        g_norms[B_SZ];
__device__ int          g_hp_bits[B_SZ];   // hardest positive dist^2, float bits
__device__ int          g_hn_bits[B_SZ];   // hardest negative dist^2, float bits
__device__ int          g_labels[B_SZ];
__device__ unsigned int g_tiles_done;

__device__ __half  g_xh[B_SZ * D_SZ];

// ------------------------- PTX helpers -------------------------
__device__ __forceinline__ uint32_t smem_u32(const void* p) {
    uint32_t a;
    asm("{ .reg .u64 t; cvta.to.shared.u64 t, %1; cvt.u32.u64 %0, t; }" : "=r"(a) : "l"(p));
    return a;
}
#define CP_ASYNC16(dst, src) \
    asm volatile("cp.async.cg.shared.global [%0], [%1], 16;" :: "r"(dst), "l"(src) : "memory")
#define CP_ASYNC_COMMIT() asm volatile("cp.async.commit_group;" ::: "memory")
#define CP_ASYNC_WAIT(n)  asm volatile("cp.async.wait_group %0;" :: "n"(n) : "memory")

__device__ __forceinline__ void ldsm_x4(uint32_t* r, uint32_t addr) {
    asm volatile("ldmatrix.sync.aligned.m8n8.x4.shared.b16 {%0,%1,%2,%3}, [%4];"
        : "=r"(r[0]), "=r"(r[1]), "=r"(r[2]), "=r"(r[3]) : "r"(addr));
}
__device__ __forceinline__ void mma16816(float* c, const uint32_t* a, const uint32_t* b) {
    asm volatile("mma.sync.aligned.m16n8k16.row.col.f32.f16.f16.f32 "
        "{%0,%1,%2,%3}, {%4,%5,%6,%7}, {%8,%9}, {%0,%1,%2,%3};"
        : "+f"(c[0]), "+f"(c[1]), "+f"(c[2]), "+f"(c[3])
        : "r"(a[0]), "r"(a[1]), "r"(a[2]), "r"(a[3]), "r"(b[0]), "r"(b[1]));
}

// ------------------------- fused prep -------------------------
// All blocks: row norms + fp16 convert + hp/hn init (one warp per row).
// Block 0 additionally: label dtype detect + normalize, reset done-counter.
__global__ void prep_kernel(const float* __restrict__ X, const void* __restrict__ labp) {
    if (blockIdx.x == 0) {
        __shared__ int is64;
        if (threadIdx.x == 0) {
            const long long* lab64 = (const long long*)labp;
            int ok = 1;
            #pragma unroll
            for (int k = 0; k < 16; k++) {
                long long v = lab64[k];
                if (v < 0 || v >= (1LL << 31)) ok = 0;
            }
            is64 = ok;
            g_tiles_done = 0u;
        }
        __syncthreads();
        const int use64 = is64;
        #pragma unroll
        for (int i = 0; i < B_SZ / 256; i++) {
            int idx = threadIdx.x + i * 256;
            g_labels[idx] = use64 ? (int)((const long long*)labp)[idx]
                                  : ((const int*)labp)[idx];
        }
    }

    const int w    = blockIdx.x * 8 + (threadIdx.x >> 5);
    const int lane = threadIdx.x & 31;
    const float4* row = (const float4*)(X + (size_t)w * D_SZ);
    uint2*        dst = (uint2*)(g_xh + (size_t)w * D_SZ);

    // issue all loads first (MLP=4), then compute
    float4 v[4];
    #pragma unroll
    for (int i = 0; i < 4; i++) v[i] = row[lane + 32 * i];

    float s = 0.f;
    #pragma unroll
    for (int i = 0; i < 4; i++) {
        s = fmaf(v[i].x, v[i].x, s);
        s = fmaf(v[i].y, v[i].y, s);
        s = fmaf(v[i].z, v[i].z, s);
        s = fmaf(v[i].w, v[i].w, s);
        __half h[4];
        h[0] = __float2half_rn(v[i].x);
        h[1] = __float2half_rn(v[i].y);
        h[2] = __float2half_rn(v[i].z);
        h[3] = __float2half_rn(v[i].w);
        dst[lane + 32 * i] = *(uint2*)h;
    }
    #pragma unroll
    for (int m = 16; m >= 1; m >>= 1)
        s += __shfl_down_sync(0xffffffffu, s, m);
    if (lane == 0) {
        g_norms[w]   = s;
        g_hp_bits[w] = (int)0xFF800000;  // -inf
        g_hn_bits[w] = 0x7F800000;       // +inf
    }
}

// ------------------------- chunk loader -------------------------
// 2 tiles (A, B), 128 rows x 64 fp16 each (128B rows), SW128 swizzled.
__device__ __forceinline__ void load_chunk(int chunk, uint32_t bufBase,
                                           int rowBase, int colBase, int tid) {
    const int k0 = chunk * KCHUNK;
    const __half* srcA = g_xh + (size_t)rowBase * D_SZ;
    const __half* srcB = g_xh + (size_t)colBase * D_SZ;
    #pragma unroll
    for (int i = 0; i < 8; i++) {
        int seg  = tid + i * 256;          // 0..2047
        int c16  = seg & 7;                // 16B segment within row
        int row  = (seg >> 3) & 127;
        int tile = seg >> 10;              // 0 = A, 1 = B
        uint32_t off = (uint32_t)(row * 128 + c16 * 16);
        uint32_t sw  = off ^ ((off >> 3) & 0x70);
        uint32_t dst = bufBase + (uint32_t)tile * TILE_BYTES + sw;
        const __half* base = tile ? srcB : srcA;
        const char* src = (const char*)base + ((size_t)row * D_SZ + k0 + c16 * 8) * 2;
        CP_ASYNC16(dst, src);
    }
    CP_ASYNC_COMMIT();
}

// ------------------------- main tensor-core tile kernel -------------------------
__global__ __launch_bounds__(256, 2) void tile_kernel(float* __restrict__ out) {
    extern __shared__ char dsmem[];
    __shared__ int   labB[BN];
    __shared__ float nrmB[BN];
    __shared__ int   lastFlag;
    __shared__ float redS[8];
    __shared__ int   redC[8];

    // ---- triangular tile decode: blockIdx.x -> (by, bx), bx >= by ----
    const int t = blockIdx.x;
    float ff = (float)(2 * NB + 1);
    int by = (int)((ff - sqrtf(ff * ff - 8.0f * (float)t)) * 0.5f);
    if (by < 0) by = 0;
    if (by > NB - 1) by = NB - 1;
    while (by > 0 && (by * NB - by * (by - 1) / 2) > t) by--;
    while (((by + 1) * NB - (by + 1) * by / 2) <= t) by++;
    const int bx   = by + (t - (by * NB - by * (by - 1) / 2));
    const bool diag = (bx == by);

    const int rowBase = by * BM;
    const int colBase = bx * BN;
    const int tid  = threadIdx.x;
    const int wid  = tid >> 5;
    const int lane = tid & 31;

    uint32_t dynBase = (smem_u32(dsmem) + 1023u) & ~1023u;

    if (tid < BN) {
        labB[tid] = g_labels[colBase + tid];
        nrmB[tid] = g_norms[colBase + tid];
    }

    // ---- prologue loads ----
    load_chunk(0, dynBase, rowBase, colBase, tid);
    load_chunk(1, dynBase + BUF_BYTES, rowBase, colBase, tid);

    // ---- per-thread ldmatrix address parts ----
    const int aRowIn = (lane & 7) + ((lane >> 3) & 1) * 8;
    const int aKH    = ((lane >> 4) & 1) * 16;            // bytes
    const int bNIn = (lane & 7) + ((lane >> 4) & 1) * 8;
    const int bKH  = ((lane >> 3) & 1) * 16;              // bytes

    const int warpRow0 = (wid & 1) * 64;                  // rows within tile
    const int warpCol0 = (wid >> 1) * 32;                 // cols within tile

    uint32_t aOff[4];
    #pragma unroll
    for (int fm = 0; fm < 4; fm++)
        aOff[fm] = (uint32_t)(warpRow0 + fm * 16 + aRowIn) * 128u;
    const uint32_t aMsk = (uint32_t)(aRowIn & 7) << 4;
    uint32_t bOff[2];
    bOff[0] = (uint32_t)(warpCol0 + bNIn) * 128u;
    bOff[1] = (uint32_t)(warpCol0 + 16 + bNIn) * 128u;
    const uint32_t bMsk = (uint32_t)(bNIn & 7) << 4;

    float Cacc[4][4][4];
    #pragma unroll
    for (int i = 0; i < 4; i++)
        #pragma unroll
        for (int j = 0; j < 4; j++)
            #pragma unroll
            for (int k = 0; k < 4; k++) Cacc[i][j][k] = 0.f;

    // ---- pipelined main loop over 8 K-chunks (R13 structure) ----
    for (int c = 0; c < NCHUNK; c++) {
        if (c < NCHUNK - 1) { CP_ASYNC_WAIT(1); } else { CP_ASYNC_WAIT(0); }
        __syncthreads();                       // chunk c resident (and labB on c==0)

        const uint32_t bb = dynBase + (uint32_t)(c & 1) * BUF_BYTES;
        const uint32_t sA = bb;
        const uint32_t sB = bb + TILE_BYTES;

        #pragma unroll
        for (int ks = 0; ks < 4; ks++) {
            const uint32_t akb = ((uint32_t)(ks * 32 + aKH)) ^ aMsk;
            const uint32_t bkb = ((uint32_t)(ks * 32 + bKH)) ^ bMsk;
            // batch ALL ldsm for this ks (MLP=6), then a dense MMA block
            uint32_t bh[8], a[16];
            ldsm_x4(bh,     sB + bOff[0] + bkb);
            ldsm_x4(bh + 4, sB + bOff[1] + bkb);
            #pragma unroll
            for (int fm = 0; fm < 4; fm++)
                ldsm_x4(a + 4 * fm, sA + aOff[fm] + akb);
            #pragma unroll
            for (int fm = 0; fm < 4; fm++)
                #pragma unroll
                for (int fn = 0; fn < 4; fn++)
                    mma16816(Cacc[fm][fn], a + 4 * fm, bh + fn * 2);
        }

        if (c + 2 < NCHUNK) {
            __syncthreads();                   // all warps done reading this buffer
            load_chunk(c + 2, dynBase + (uint32_t)(c & 1) * BUF_BYTES,
                       rowBase, colBase, tid);
        }
    }

    // ---- epilogue: d^2 + hardest pos/neg (selection in d^2 space) ----
    const float NEG_INF = __int_as_float(0xFF800000);
    const float POS_INF = __int_as_float(0x7F800000);
    const int quad = lane >> 2;      // 0..7  (row within 8-row group)
    const int pos  = lane & 3;       // 0..3  (col pair)

    int   laR[8], giR[8];
    float naR[8];
    #pragma unroll
    for (int fm = 0; fm < 4; fm++)
        #pragma unroll
        for (int ar = 0; ar < 2; ar++) {
            int gi = rowBase + warpRow0 + fm * 16 + ar * 8 + quad;
            giR[fm * 2 + ar] = gi;
            laR[fm * 2 + ar] = g_labels[gi];
            naR[fm * 2 + ar] = g_norms[gi];
        }
    int   lbC[8], gjC[8];
    float nbC[8];
    #pragma unroll
    for (int fn = 0; fn < 4; fn++)
        #pragma unroll
        for (int cb = 0; cb < 2; cb++) {
            int cl = warpCol0 + fn * 8 + pos * 2 + cb;
            gjC[fn * 2 + cb] = colBase + cl;
            lbC[fn * 2 + cb] = labB[cl];
            nbC[fn * 2 + cb] = nrmB[cl];
        }

    float hpR[8], hnR[8], hpc[8], hnc[8];
    #pragma unroll
    for (int i = 0; i < 8; i++) { hpR[i] = NEG_INF; hnR[i] = POS_INF; hpc[i] = NEG_INF; hnc[i] = POS_INF; }

    #pragma unroll
    for (int fm = 0; fm < 4; fm++)
        #pragma unroll
        for (int fn = 0; fn < 4; fn++)
            #pragma unroll
            for (int ar = 0; ar < 2; ar++)
                #pragma unroll
                for (int cb = 0; cb < 2; cb++) {
                    int ri = fm * 2 + ar, ci = fn * 2 + cb;
                    float dot = Cacc[fm][fn][ar * 2 + cb];
                    // d^2, clamped at 0 — monotone proxy for d
                    float sq  = fmaxf(fmaf(-2.f, dot, naR[ri] + nbC[ci]), 0.f);
                    if (laR[ri] == lbC[ci]) {
                        if (giR[ri] != gjC[ci]) {
                            hpR[ri] = fmaxf(hpR[ri], sq);
                            hpc[ci] = fmaxf(hpc[ci], sq);
                        }
                    } else {
                        hnR[ri] = fminf(hnR[ri], sq);
                        hnc[ci] = fminf(hnc[ci], sq);
                    }
                }

    // row stats: reduce over the 4 'pos' lanes sharing a row
    #pragma unroll
    for (int i = 0; i < 8; i++) {
        float a = hpR[i], b = hnR[i];
        a = fmaxf(a, __shfl_xor_sync(0xffffffffu, a, 1));
        a = fmaxf(a, __shfl_xor_sync(0xffffffffu, a, 2));
        b = fminf(b, __shfl_xor_sync(0xffffffffu, b, 1));
        b = fminf(b, __shfl_xor_sync(0xffffffffu, b, 2));
        if (pos == 0) {
            atomicMax(&g_hp_bits[giR[i]], __float_as_int(a));
            atomicMin(&g_hn_bits[giR[i]], __float_as_int(b));
        }
    }
    // column stats (symmetry): reduce over the 8 'quad' lanes sharing a column
    if (!diag) {
        #pragma unroll
        for (int i = 0; i < 8; i++) {
            float a = hpc[i], b = hnc[i];
            a = fmaxf(a, __shfl_xor_sync(0xffffffffu, a, 4));
            a = fmaxf(a, __shfl_xor_sync(0xffffffffu, a, 8));
            a = fmaxf(a, __shfl_xor_sync(0xffffffffu, a, 16));
            b = fminf(b, __shfl_xor_sync(0xffffffffu, b, 4));
            b = fminf(b, __shfl_xor_sync(0xffffffffu, b, 8));
            b = fminf(b, __shfl_xor_sync(0xffffffffu, b, 16));
            if (quad == 0) {
                atomicMax(&g_hp_bits[gjC[i]], __float_as_int(a));
                atomicMin(&g_hn_bits[gjC[i]], __float_as_int(b));
            }
        }
    }

    // ---- fused finalize: last CTA reduces hp/hn into the scalar loss ----
    __threadfence();                       // make this CTA's atomics visible
    __syncthreads();                       // all threads' atomics issued
    if (tid == 0) {
        unsigned int prev = atomicAdd(&g_tiles_done, 1u);
        lastFlag = (prev == NTILES - 1u);
    }
    __syncthreads();
    if (!lastFlag) return;

    // this CTA observes all other CTAs' atomics (counter was written after
    // their threadfence; atomicAdd ordering gives acquire semantics here)
    float sum = 0.f;
    int   cnt = 0;
    #pragma unroll
    for (int i = 0; i < B_SZ / 256; i++) {
        int idx = tid + i * 256;
        int hpb = g_hp_bits[idx];
        int hnb = g_hn_bits[idx];
        if (hpb != (int)0xFF800000 && hnb != 0x7F800000) {
            // sqrt deferred to here: selection was in d^2 space
            float hp = sqrtf(__int_as_float(hpb));
            float hn = sqrtf(__int_as_float(hnb));
            sum += fmaxf(hp - hn + MARGIN_F, 0.f);
            cnt += 1;
        }
    }
    #pragma unroll
    for (int m = 16; m >= 1; m >>= 1) {
        sum += __shfl_xor_sync(0xffffffffu, sum, m);
        cnt += __shfl_xor_sync(0xffffffffu, cnt, m);
    }
    if (lane == 0) { redS[wid] = sum; redC[wid] = cnt; }
    __syncthreads();
    if (wid == 0) {
        float s2 = (lane < 8) ? redS[lane] : 0.f;
        int   c2 = (lane < 8) ? redC[lane] : 0;
        #pragma unroll
        for (int m = 4; m >= 1; m >>= 1) {
            s2 += __shfl_xor_sync(0xffffffffu, s2, m);
            c2 += __shfl_xor_sync(0xffffffffu, c2, m);
        }
        if (lane == 0) out[0] = (c2 > 0) ? (s2 / (float)c2) : 0.f;
    }
}

// ------------------------- launch -------------------------
extern "C" void kernel_launch(void* const* d_in, const int* in_sizes, int n_in,
                              void* d_out, int out_size) {
    const float* X    = (const float*)d_in[0];
    const void*  labp = d_in[1];
    float*       out  = (float*)d_out;

    // idempotent, host-side, not a stream op: safe under graph capture
    cudaFuncSetAttribute(tile_kernel, cudaFuncAttributeMaxDynamicSharedMemorySize, SMEM_DYN);

    prep_kernel<<<B_SZ / 8, 256>>>(X, labp);
    tile_kernel<<<NTILES, 256, SMEM_DYN>>>(out);
}